// round 8
// baseline (speedup 1.0000x reference)
#include <cuda_runtime.h>
#include <math.h>

#ifndef M_PI
#define M_PI 3.14159265358979323846
#endif

#define NBLK  148
#define NT    448
#define TXDIM 421
#define TYDIM 421
#define NRMAX 3
#define SRCI  210
#define SRCJ  210
#define RSLOT 4
#define SRCBUF 512

// Seq-stamped packets, 3 per direction, one exchange per 2 steps.
// pktU (from block b, consumed by b+1 as its LOWER ghosts):
//   u0={ez_last, ez_last-1, hy_last, seq} u1={hy_last-1, eold_last, jz_last, seq}
//   u2={jold_last, hx_last, hxm_last, seq}
// pktD (from block b, consumed by b-1 as its UPPER ghosts):
//   d0={ez0, ez1, hy0, seq} d1={eold0, jz0, jold0, seq} d2={hx0, hxm0, 0, seq}
__device__ float4   g_pktU[3][RSLOT][NBLK][NT];
__device__ float4   g_pktD[3][RSLOT][NBLK][NT];
__device__ unsigned g_epoch;   // monotonic across graph replays

static __device__ __forceinline__ void st_pkt(float4* p, float x, float y, float z, unsigned seq) {
    asm volatile("st.volatile.global.v4.f32 [%0], {%1,%2,%3,%4};"
                 :: "l"(p), "f"(x), "f"(y), "f"(z), "f"(__uint_as_float(seq)) : "memory");
}
static __device__ __forceinline__ float4 ld_pkt(const float4* p) {
    float4 v;
    asm volatile("ld.volatile.global.v4.f32 {%0,%1,%2,%3}, [%4];"
                 : "=f"(v.x), "=f"(v.y), "=f"(v.z), "=f"(v.w) : "l"(p) : "memory");
    return v;
}

__global__ void __launch_bounds__(NT, 1)
fdtd_mlor_kernel(const float* __restrict__ src, int src_len,
                 const float* __restrict__ C1a, const float* __restrict__ C2a,
                 const float* __restrict__ Cbdxa, const float* __restrict__ Cbdya,
                 const float* __restrict__ dbhxa, const float* __restrict__ dbhya,
                 const float* __restrict__ Caa, const float* __restrict__ Cba,
                 const float* __restrict__ Cca, const float* __restrict__ Cda,
                 const float* __restrict__ Cea,
                 const float* __restrict__ sig_ex, const float* __restrict__ sig_ey,
                 const float* __restrict__ sig_hx, const float* __restrict__ sig_hy,
                 const int* __restrict__ nsp,
                 float* __restrict__ out,
                 float kE, float kMu)
{
    const int bid = blockIdx.x;
    const int j   = threadIdx.x;

    const float ca   = Caa[0], cb = Cba[0], cc = Cca[0], cd = Cda[0], ce = Cea[0];
    const float C1   = C1a[0], C2 = C2a[0];
    const float Cbdx = Cbdxa[0], Cbdy = Cbdya[0];
    const float dbhx = dbhxa[0], dbhy = dbhya[0];

    int n = nsp ? nsp[0] : 200;
    if (n > src_len) n = src_len;
    if (n < 0) n = 0;
    const int npairs = n >> 1;
    const int rem    = n & 1;

    const int r0 = (bid * TXDIM) / NBLK;
    const int r1 = ((bid + 1) * TXDIM) / NBLK;
    const int nrows = r1 - r0;                 // 2 or 3
    const bool hasL = (bid > 0);
    const bool hasU = (bid < NBLK - 1);

    const bool colE = (j < TYDIM);
    const bool colH = (j < TYDIM - 1);
    const bool colM = (j >= 1 && j < TYDIM);

    // Column decay factors
    float cEyE = 1.f, cEyMu = 1.f, cHyMu = 1.f, cHyMuM = 1.f;
    if (colE) { float s = sig_ey[j]; cEyE = expf(-s * kE); cEyMu = expf(-s * kMu); }
    if (colH) cHyMu  = expf(-sig_hy[j]     * kMu);
    if (colM) cHyMuM = expf(-sig_hy[j - 1] * kMu);

    float fDe[NRMAX], fHx[NRMAX], fHxm[NRMAX], fHy[NRMAX];
    #pragma unroll
    for (int r = 0; r < NRMAX; ++r) {
        fDe[r] = 0.f; fHx[r] = 0.f; fHxm[r] = 0.f; fHy[r] = 0.f;
        if (r < nrows) {
            int i = r0 + r;
            float sx  = sig_ex[i];
            float rMu = expf(-sx * kMu);
            fDe[r]  = expf(-sx * kE) * cEyE;
            fHx[r]  = rMu * cHyMu;
            fHxm[r] = rMu * cHyMuM;
            fHy[r]  = (i < TXDIM - 1) ? expf(-sig_hx[i] * kMu) * cEyMu : 0.f;
        }
    }
    // Ghost-row coefficients (identical formulas -> bitwise-identical recomputation)
    float fDeGl = 0.f, fHxGl = 0.f, fHxmGl = 0.f, fHyL0 = 0.f, fHyL1 = 0.f;
    if (hasL && colE) {
        float sx  = sig_ex[r0 - 1];
        float rMu = expf(-sx * kMu);
        fDeGl  = expf(-sx * kE) * cEyE;
        fHxGl  = (colH ? rMu * cHyMu : 0.f);
        fHxmGl = (colM ? rMu * cHyMuM : 0.f);
        fHyL0  = expf(-sig_hx[r0 - 1] * kMu) * cEyMu;
        fHyL1  = expf(-sig_hx[r0 - 2] * kMu) * cEyMu;
    }
    float fDeGu = 0.f, fHxGu = 0.f, fHxmGu = 0.f, fHyU0 = 0.f;
    if (hasU && colE) {
        float sx  = sig_ex[r1];
        float rMu = expf(-sx * kMu);
        fDeGu  = expf(-sx * kE) * cEyE;
        fHxGu  = (colH ? rMu * cHyMu : 0.f);
        fHxmGu = (colM ? rMu * cHyMuM : 0.f);
        fHyU0  = expf(-sig_hx[r1] * kMu) * cEyMu;
    }

    // Own-row state (registers, whole run)
    float ez[NRMAX]   = {0.f, 0.f, 0.f};
    float eold[NRMAX] = {0.f, 0.f, 0.f};
    float jz[NRMAX]   = {0.f, 0.f, 0.f};
    float jold[NRMAX] = {0.f, 0.f, 0.f};
    float hx[NRMAX]   = {0.f, 0.f, 0.f};
    float hxm[NRMAX]  = {0.f, 0.f, 0.f};
    float hy[NRMAX]   = {0.f, 0.f, 0.f};
    // Ghost state (refreshed from packets every pair)
    float ezGl0 = 0.f, ezGl1 = 0.f, hyGl0 = 0.f, hyGl1 = 0.f;
    float eoldGl = 0.f, jzGl = 0.f, joldGl = 0.f, hxGl = 0.f, hxmGl = 0.f;
    float ezGu0 = 0.f, ezGu1 = 0.f, hyGu0 = 0.f;
    float eoldGu = 0.f, jzGu = 0.f, joldGu = 0.f, hxGu = 0.f, hxmGu = 0.f;

    __shared__ float sEz[2][NRMAX][NT + 4];  // ping-pong own Ez rows
    __shared__ float sgEzL[NT + 4];          // ghost Ez (lower, time t)
    __shared__ float sgEzU[NT + 4];          // ghost Ez (upper, time t)
    __shared__ float sSrc[SRCBUF];

    #pragma unroll
    for (int r = 0; r < NRMAX; ++r) { sEz[0][r][j] = 0.f; }
    sgEzL[j] = 0.f; sgEzU[j] = 0.f;
    if (j < 4) {
        #pragma unroll
        for (int r = 0; r < NRMAX; ++r) { sEz[0][r][NT + j] = 0.f; sEz[1][r][NT + j] = 0.f; }
        sgEzL[NT + j] = 0.f; sgEzU[NT + j] = 0.f;
    }
    if (j < n && j < SRCBUF) sSrc[j] = src[j];

    const unsigned base = *(volatile unsigned*)&g_epoch;

#define EUPD(r, hyBelow, buf, srcv)                                                \
    do {                                                                           \
        int i_ = r0 + (r);                                                         \
        float eznew_ = 0.f;                                                        \
        if (i_ >= 1 && i_ <= TXDIM - 2 && j >= 1 && j <= TYDIM - 2) {              \
            float chy_ = hy[(r)] - (hyBelow);                                      \
            float chx_ = hx[(r)] - hxm[(r)];                                       \
            eznew_ = fDe[(r)] * (C1 * ez[(r)] + Cbdx * chy_ - Cbdy * chx_          \
                                 - C2 * phi[(r)]);                                 \
            if (i_ == SRCI && j == SRCJ) eznew_ += (srcv);                         \
        }                                                                          \
        jold[(r)] = jz[(r)]; jz[(r)] = jpart[(r)] + cc * eznew_;                   \
        eold[(r)] = ez[(r)]; ez[(r)] = eznew_;                                     \
        sEz[(buf)][(r)][j] = eznew_;                                               \
    } while (0)

#define PHIPREP()                                                                  \
    do {                                                                           \
        _Pragma("unroll")                                                          \
        for (int r = 0; r < NRMAX; ++r) {                                          \
            if (r < nrows) {                                                       \
                float jp = ca * jz[r] + cb * jold[r] + cd * ez[r] + ce * eold[r];  \
                jpart[r] = jp;                                                     \
                phi[r]   = jp + jz[r];                                             \
            }                                                                      \
        }                                                                          \
    } while (0)

#define POLL_INGEST(PP)                                                            \
    do {                                                                           \
        const int sp_ = ((PP) - 1) & (RSLOT - 1);                                  \
        const unsigned want_ = base + (unsigned)(PP);                              \
        if (colE && (PP) > 0) {                                                    \
            if (hasL) {                                                            \
                const float4* a0 = &g_pktU[0][sp_][bid - 1][j];                    \
                const float4* a1 = &g_pktU[1][sp_][bid - 1][j];                    \
                const float4* a2 = &g_pktU[2][sp_][bid - 1][j];                    \
                float4 u0 = ld_pkt(a0), u1 = ld_pkt(a1), u2 = ld_pkt(a2);          \
                while (__float_as_uint(u0.w) < want_) u0 = ld_pkt(a0);             \
                while (__float_as_uint(u1.w) < want_) u1 = ld_pkt(a1);             \
                while (__float_as_uint(u2.w) < want_) u2 = ld_pkt(a2);             \
                ezGl0 = u0.x; ezGl1 = u0.y; hyGl0 = u0.z;                          \
                hyGl1 = u1.x; eoldGl = u1.y; jzGl = u1.z;                          \
                joldGl = u2.x; hxGl = u2.y; hxmGl = u2.z;                          \
                sgEzL[j] = ezGl0;                                                  \
            }                                                                      \
            if (hasU) {                                                            \
                const float4* b0 = &g_pktD[0][sp_][bid + 1][j];                    \
                const float4* b1 = &g_pktD[1][sp_][bid + 1][j];                    \
                const float4* b2 = &g_pktD[2][sp_][bid + 1][j];                    \
                float4 d0 = ld_pkt(b0), d1 = ld_pkt(b1), d2 = ld_pkt(b2);          \
                while (__float_as_uint(d0.w) < want_) d0 = ld_pkt(b0);             \
                while (__float_as_uint(d1.w) < want_) d1 = ld_pkt(b1);             \
                while (__float_as_uint(d2.w) < want_) d2 = ld_pkt(b2);             \
                ezGu0 = d0.x; ezGu1 = d0.y; hyGu0 = d0.z;                          \
                eoldGu = d1.x; jzGu = d1.y; joldGu = d1.z;                         \
                hxGu = d2.x; hxmGu = d2.y;                                         \
                sgEzU[j] = ezGu0;                                                  \
            }                                                                      \
        }                                                                          \
    } while (0)

    __syncthreads();   // zeros + sSrc visible

    float phi[NRMAX], jpart[NRMAX];

    for (int p = 0; p < npairs; ++p) {
        const int tA = 2 * p, tB = tA + 1;
        const float sA = (tA < SRCBUF) ? sSrc[tA] : 0.f;
        const float sB = (tB < SRCBUF) ? sSrc[tB] : 0.f;

        PHIPREP();                // state t — overlaps the poll RT below
        POLL_INGEST(p);
        __syncthreads();          // BAR1: sgEz + previous pair's sEz[0] ready

        // ================= STEP A (t -> t+1) =================
        if (colE) {
            #pragma unroll
            for (int r = 0; r < NRMAX; ++r) {
                if (r < nrows) {
                    if (colH) hx[r]  = fHx[r]  * (hx[r]  - dbhx * (sEz[0][r][j + 1] - ez[r]));
                    if (colM) hxm[r] = fHxm[r] * (hxm[r] - dbhx * (ez[r] - sEz[0][r][j - 1]));
                    if (r + 1 < nrows) hy[r] = fHy[r] * (hy[r] + dbhy * (ez[r + 1] - ez[r]));
                }
            }
            if (nrows == 3) hy[2] = fHy[2] * (hy[2] + dbhy * (ezGu0 - ez[2]));
            else            hy[1] = fHy[1] * (hy[1] + dbhy * (ezGu0 - ez[1]));

            // Ghost lower: H(t+1) + E(t+1) at row r0-1
            if (hasL) {
                hyGl1 = fHyL1 * (hyGl1 + dbhy * (ezGl0 - ezGl1));
                hyGl0 = fHyL0 * (hyGl0 + dbhy * (ez[0] - ezGl0));
                if (colH) hxGl  = fHxGl  * (hxGl  - dbhx * (sgEzL[j + 1] - ezGl0));
                if (colM) hxmGl = fHxmGl * (hxmGl - dbhx * (ezGl0 - sgEzL[j - 1]));
                float ezn = 0.f;
                if (j >= 1 && j <= TYDIM - 2) {
                    float phiG = (ca + 1.f) * jzGl + cb * joldGl + cd * ezGl0 + ce * eoldGl;
                    ezn = fDeGl * (C1 * ezGl0 + Cbdx * (hyGl0 - hyGl1)
                                   - Cbdy * (hxGl - hxmGl) - C2 * phiG);
                    if (r0 - 1 == SRCI && j == SRCJ) ezn += sA;
                }
                ezGl0 = ezn;
            }
            // Ghost upper: H(t+1) + E(t+1) at row r1
            if (hasU) {
                hyGu0 = fHyU0 * (hyGu0 + dbhy * (ezGu1 - ezGu0));
                if (colH) hxGu  = fHxGu  * (hxGu  - dbhx * (sgEzU[j + 1] - ezGu0));
                if (colM) hxmGu = fHxmGu * (hxmGu - dbhx * (ezGu0 - sgEzU[j - 1]));
                float hyOwnTop = (nrows == 3) ? hy[2] : hy[1];
                float ezn = 0.f;
                if (j >= 1 && j <= TYDIM - 2) {
                    float phiG = (ca + 1.f) * jzGu + cb * joldGu + cd * ezGu0 + ce * eoldGu;
                    ezn = fDeGu * (C1 * ezGu0 + Cbdx * (hyGu0 - hyOwnTop)
                                   - Cbdy * (hxGu - hxmGu) - C2 * phiG);
                    if (r1 == SRCI && j == SRCJ) ezn += sA;
                }
                ezGu0 = ezn;
            }

            // Own E (t+1), write buffer 1
            EUPD(0, hyGl0, 1, sA);
            EUPD(1, hy[0], 1, sA);
            if (nrows == 3) EUPD(2, hy[1], 1, sA);
        }
        __syncthreads();          // BAR2: sEz[1] ready

        // ================= STEP B (t+1 -> t+2) =================
        if (colE) {
            PHIPREP();            // state t+1
            #pragma unroll
            for (int r = 0; r < NRMAX; ++r) {
                if (r < nrows) {
                    if (colH) hx[r]  = fHx[r]  * (hx[r]  - dbhx * (sEz[1][r][j + 1] - ez[r]));
                    if (colM) hxm[r] = fHxm[r] * (hxm[r] - dbhx * (ez[r] - sEz[1][r][j - 1]));
                    if (r + 1 < nrows) hy[r] = fHy[r] * (hy[r] + dbhy * (ez[r + 1] - ez[r]));
                }
            }
            if (nrows == 3) hy[2] = fHy[2] * (hy[2] + dbhy * (ezGu0 - ez[2]));
            else            hy[1] = fHy[1] * (hy[1] + dbhy * (ezGu0 - ez[1]));
            hyGl0 = fHyL0 * (hyGl0 + dbhy * (ez[0] - ezGl0));   // Hy(r0-1, t+2)

            // Own E (t+2), write buffer 0 — COMPLETE ALL ROWS FIRST
            EUPD(0, hyGl0, 0, sB);
            EUPD(1, hy[0], 0, sB);
            if (nrows == 3) EUPD(2, hy[1], 0, sB);

            // Publish boundary state at t+2 (all registers now current)
            const int s = p & (RSLOT - 1);
            const unsigned seq = base + (unsigned)p + 1u;
            st_pkt(&g_pktD[0][s][bid][j], ez[0], ez[1], hy[0], seq);
            st_pkt(&g_pktD[1][s][bid][j], eold[0], jz[0], jold[0], seq);
            st_pkt(&g_pktD[2][s][bid][j], hx[0], hxm[0], 0.f, seq);
            if (nrows == 3) {
                st_pkt(&g_pktU[0][s][bid][j], ez[2], ez[1], hy[2], seq);
                st_pkt(&g_pktU[1][s][bid][j], hy[1], eold[2], jz[2], seq);
                st_pkt(&g_pktU[2][s][bid][j], jold[2], hx[2], hxm[2], seq);
            } else {
                st_pkt(&g_pktU[0][s][bid][j], ez[1], ez[0], hy[1], seq);
                st_pkt(&g_pktU[1][s][bid][j], hy[0], eold[1], jz[1], seq);
                st_pkt(&g_pktU[2][s][bid][j], jold[1], hx[1], hxm[1], seq);
            }
        }
        // next pair's BAR1 protects sEz[0]
    }

    // ================= Odd tail step =================
    if (rem) {
        const int tT = 2 * npairs;
        const float sT = (tT < SRCBUF) ? sSrc[tT] : 0.f;
        PHIPREP();
        POLL_INGEST(npairs);
        __syncthreads();
        if (colE) {
            #pragma unroll
            for (int r = 0; r < NRMAX; ++r) {
                if (r < nrows) {
                    if (colH) hx[r]  = fHx[r]  * (hx[r]  - dbhx * (sEz[0][r][j + 1] - ez[r]));
                    if (colM) hxm[r] = fHxm[r] * (hxm[r] - dbhx * (ez[r] - sEz[0][r][j - 1]));
                    if (r + 1 < nrows) hy[r] = fHy[r] * (hy[r] + dbhy * (ez[r + 1] - ez[r]));
                }
            }
            if (nrows == 3) hy[2] = fHy[2] * (hy[2] + dbhy * (ezGu0 - ez[2]));
            else            hy[1] = fHy[1] * (hy[1] + dbhy * (ezGu0 - ez[1]));
            hyGl0 = fHyL0 * (hyGl0 + dbhy * (ez[0] - ezGl0));
            EUPD(0, hyGl0, 1, sT);
            EUPD(1, hy[0], 1, sT);
            if (nrows == 3) EUPD(2, hy[1], 1, sT);
        }
    }

    #pragma unroll
    for (int r = 0; r < NRMAX; ++r) {
        if (r < nrows && colE) out[(r0 + r) * TYDIM + j] = ez[r];
    }

    if (j == 0) *(volatile unsigned*)&g_epoch = base + (unsigned)npairs;

#undef EUPD
#undef PHIPREP
#undef POLL_INGEST
}

extern "C" void kernel_launch(void* const* d_in, const int* in_sizes, int n_in,
                              void* d_out, int out_size) {
    const float* src    = (const float*)d_in[0];
    const float* C1a    = (const float*)d_in[1];
    const float* C2a    = (const float*)d_in[2];
    const float* Cbdxa  = (const float*)d_in[3];
    const float* Cbdya  = (const float*)d_in[4];
    const float* dbhxa  = (const float*)d_in[5];
    const float* dbhya  = (const float*)d_in[6];
    const float* Caa    = (const float*)d_in[7];
    const float* Cba    = (const float*)d_in[8];
    const float* Cca    = (const float*)d_in[9];
    const float* Cda    = (const float*)d_in[10];
    const float* Cea    = (const float*)d_in[11];
    const float* sigex  = (const float*)d_in[12];
    const float* sigey  = (const float*)d_in[13];
    const float* sighx  = (const float*)d_in[14];
    const float* sighy  = (const float*)d_in[15];
    const int*   nsp    = (n_in >= 17) ? (const int*)d_in[16] : nullptr;

    const double EPS0 = 1e-9 / 36.0 / M_PI;
    const double MU0  = 4.0 * M_PI * 1e-7;
    const double C0   = 1.0 / sqrt(MU0 * EPS0);
    const double DX = 2.5e-8, DY = 2.5e-8;
    const double DT = 0.99 / C0 / sqrt(1.0 / (DX * DX) + 1.0 / (DY * DY));
    const float kE  = (float)(DT / EPS0);
    const float kMu = (float)(DT / MU0);

    fdtd_mlor_kernel<<<NBLK, NT>>>(src, in_sizes[0],
                                   C1a, C2a, Cbdxa, Cbdya, dbhxa, dbhya,
                                   Caa, Cba, Cca, Cda, Cea,
                                   sigex, sigey, sighx, sighy,
                                   nsp, (float*)d_out, kE, kMu);
    (void)out_size;
}